// round 2
// baseline (speedup 1.0000x reference)
#include <cuda_runtime.h>
#include <math_constants.h>

// Problem constants (match reference)
#define D         128            // D_IN = D_OUT = 128
#define N_SRC_MAX 50000
#define N_DST_MAX 50000
#define E_MAX     1600000
#define INV_SCALE 0.25f          // 1/sqrt(128/8) = 1/4

// ---------------- scratch (no allocations allowed) ----------------
__device__ __align__(128) float g_Q[N_DST_MAX * D];
__device__ __align__(128) float g_K[N_SRC_MAX * D];
__device__ __align__(128) float g_V[N_SRC_MAX * D];
__device__ __align__(128) float g_score[E_MAX];
__device__ __align__(128) float g_m[N_DST_MAX];
__device__ __align__(128) float g_denom[N_DST_MAX];
__device__ int g_is64;           // 1 if index buffers are int64, 0 if int32

// ---------------- helpers ----------------
__device__ __forceinline__ void atomicMaxF(float* addr, float val) {
    // IEEE-754 ordering trick: int-max for >=0, uint-min for <0.
    if (val >= 0.0f) atomicMax((int*)addr, __float_as_int(val));
    else             atomicMin((unsigned int*)addr, __float_as_uint(val));
}

__device__ __forceinline__ void redAddV4(float* addr, float4 v) {
    asm volatile("red.global.add.v4.f32 [%0], {%1, %2, %3, %4};"
                 :: "l"(addr), "f"(v.x), "f"(v.y), "f"(v.z), "f"(v.w)
                 : "memory");
}

__device__ __forceinline__ int load_idx(const void* p, int i) {
    if (g_is64) return (int)((const long long*)p)[i];
    return ((const int*)p)[i];
}

// ---------------- dtype detection: are index buffers int64 or int32? ----------------
// Reads the first 64 entries of each as int64. If the data is really int32,
// an "int64" read is lo + hi*2^32 where hi is itself a valid small index ->
// value falls outside [0, n) with overwhelming probability.
__global__ void detect_idx_kernel(const void* src_idx, const void* dst_idx,
                                  int n_src, int n_dst, int E) {
    if (threadIdx.x == 0) g_is64 = 1;
    __syncthreads();
    int i = threadIdx.x;                   // 64 threads
    int limit = (E / 2 < 64) ? E / 2 : 64; // stay within buffer even if int32
    if (i < limit) {
        long long s = ((const long long*)src_idx)[i];
        long long d = ((const long long*)dst_idx)[i];
        bool ok = (s >= 0 && s < n_src && d >= 0 && d < n_dst);
        if (!ok) atomicExch(&g_is64, 0);
    }
}

// ---------------- init: m = -inf, denom = 0 ----------------
__global__ void init_kernel(int n_dst) {
    int i = blockIdx.x * blockDim.x + threadIdx.x;
    if (i < n_dst) {
        g_m[i] = -CUDART_INF_F;
        g_denom[i] = 0.0f;
    }
}

// ---------------- projection GEMM: Y[n][o] = sum_k X[n][k] * W[o][k] + b[o] ----------------
// 64 rows per block, full 128-col output width, 256 threads, 8x4 register tile.
#define PROJ_SMEM ((64 * 128 + 128 * 132) * 4)
__global__ __launch_bounds__(256) void proj_kernel(
    const float* __restrict__ X, const float* __restrict__ W,
    const float* __restrict__ b, float* __restrict__ Y, int N)
{
    extern __shared__ float sm[];
    float* Xs = sm;               // [64][128]
    float* Wt = sm + 64 * 128;    // [128][132]  (W transposed, padded row)

    const int tid  = threadIdx.x;
    const int row0 = blockIdx.x * 64;

    // Load W (row-major [o][k]) transposed into Wt[k][o]
    #pragma unroll 4
    for (int idx = tid; idx < 128 * 128; idx += 256) {
        int o = idx >> 7, k = idx & 127;
        Wt[k * 132 + o] = W[idx];
    }
    // Load X tile (float4, coalesced)
    #pragma unroll
    for (int idx = tid; idx < 64 * 32; idx += 256) {
        int r = idx >> 5, c4 = idx & 31;
        int row = row0 + r;
        float4 v = (row < N) ? ((const float4*)X)[(size_t)row * 32 + c4]
                             : make_float4(0.f, 0.f, 0.f, 0.f);
        ((float4*)Xs)[r * 32 + c4] = v;
    }
    __syncthreads();

    const int tcol = tid & 31;    // output cols tcol*4 .. tcol*4+3
    const int trow = tid >> 5;    // rows trow*8 .. trow*8+7

    float acc[8][4];
    #pragma unroll
    for (int i = 0; i < 8; i++)
        #pragma unroll
        for (int j = 0; j < 4; j++) acc[i][j] = 0.0f;

    #pragma unroll 4
    for (int k = 0; k < 128; k++) {
        float4 w = *(const float4*)&Wt[k * 132 + tcol * 4];
        #pragma unroll
        for (int i = 0; i < 8; i++) {
            float x = Xs[(trow * 8 + i) * 128 + k];   // broadcast within warp
            acc[i][0] += x * w.x;
            acc[i][1] += x * w.y;
            acc[i][2] += x * w.z;
            acc[i][3] += x * w.w;
        }
    }

    float4 bias = *(const float4*)&b[tcol * 4];
    #pragma unroll
    for (int i = 0; i < 8; i++) {
        int row = row0 + trow * 8 + i;
        if (row < N) {
            float4 r4 = make_float4(acc[i][0] + bias.x, acc[i][1] + bias.y,
                                    acc[i][2] + bias.z, acc[i][3] + bias.w);
            ((float4*)Y)[(size_t)row * 32 + tcol] = r4;
        }
    }
}

// ---------------- pass 1: edge scores + segment max ----------------
// one warp per edge
__global__ __launch_bounds__(256) void score_kernel(
    const void* __restrict__ src_idx,
    const void* __restrict__ dst_idx, int E)
{
    int warp = (blockIdx.x * blockDim.x + threadIdx.x) >> 5;
    if (warp >= E) return;
    int lane = threadIdx.x & 31;

    int s = load_idx(src_idx, warp);
    int d = load_idx(dst_idx, warp);

    float4 q = ((const float4*)(g_Q + (size_t)d * D))[lane];
    float4 k = ((const float4*)(g_K + (size_t)s * D))[lane];
    float dot = q.x * k.x + q.y * k.y + q.z * k.z + q.w * k.w;
    #pragma unroll
    for (int off = 16; off > 0; off >>= 1)
        dot += __shfl_xor_sync(0xFFFFFFFFu, dot, off);

    if (lane == 0) {
        float sc = dot * INV_SCALE;
        g_score[warp] = sc;
        atomicMaxF(&g_m[d], sc);
    }
}

// ---------------- pass 2: e = exp(score - m); out += e*V[src]; denom += e ----------------
// one warp per edge; vector reduction atomics (sm_90+)
__global__ __launch_bounds__(256) void scatter_kernel(
    const void* __restrict__ src_idx,
    const void* __restrict__ dst_idx,
    float* __restrict__ out, int E)
{
    int warp = (blockIdx.x * blockDim.x + threadIdx.x) >> 5;
    if (warp >= E) return;
    int lane = threadIdx.x & 31;

    int s = load_idx(src_idx, warp);
    int d = load_idx(dst_idx, warp);

    float w = __expf(g_score[warp] - g_m[d]);
    if (lane == 0) atomicAdd(&g_denom[d], w);

    float4 v = ((const float4*)(g_V + (size_t)s * D))[lane];
    float4 contrib = make_float4(w * v.x, w * v.y, w * v.z, w * v.w);
    redAddV4(out + (size_t)d * D + lane * 4, contrib);
}

// ---------------- pass 3: normalize ----------------
__global__ __launch_bounds__(256) void normalize_kernel(float* __restrict__ out, int n_dst) {
    int idx = blockIdx.x * blockDim.x + threadIdx.x;   // one float4 per thread
    int total = n_dst * 32;
    if (idx >= total) return;
    int n = idx >> 5;
    float den = g_denom[n];
    float inv = (den > 0.0f) ? (1.0f / den) : 0.0f;
    float4 v = ((float4*)out)[idx];
    v.x *= inv; v.y *= inv; v.z *= inv; v.w *= inv;
    ((float4*)out)[idx] = v;
}

// ---------------- launch ----------------
extern "C" void kernel_launch(void* const* d_in, const int* in_sizes, int n_in,
                              void* d_out, int out_size)
{
    const float* src_feat = (const float*)d_in[0];
    const float* dst_feat = (const float*)d_in[1];
    const void*  src_idx  = d_in[2];
    const void*  dst_idx  = d_in[3];
    const float* Wq = (const float*)d_in[4];
    const float* bq = (const float*)d_in[5];
    const float* Wk = (const float*)d_in[6];
    const float* bk = (const float*)d_in[7];
    const float* Wv = (const float*)d_in[8];
    const float* bv = (const float*)d_in[9];
    float* out = (float*)d_out;

    int n_src = in_sizes[0] / D;
    int n_dst = in_sizes[1] / D;
    int E     = in_sizes[2];

    static int smem_set = 0;
    if (!smem_set) {
        cudaFuncSetAttribute(proj_kernel, cudaFuncAttributeMaxDynamicSharedMemorySize, PROJ_SMEM);
        smem_set = 1;
    }

    float* Qp; cudaGetSymbolAddress((void**)&Qp, g_Q);
    float* Kp; cudaGetSymbolAddress((void**)&Kp, g_K);
    float* Vp; cudaGetSymbolAddress((void**)&Vp, g_V);

    // out := 0 (it is poisoned to 0xAA before timing)
    cudaMemsetAsync(d_out, 0, (size_t)out_size * sizeof(float), 0);

    detect_idx_kernel<<<1, 64>>>(src_idx, dst_idx, n_src, n_dst, E);
    init_kernel<<<(n_dst + 255) / 256, 256>>>(n_dst);

    proj_kernel<<<(n_dst + 63) / 64, 256, PROJ_SMEM>>>(dst_feat, Wq, bq, Qp, n_dst);
    proj_kernel<<<(n_src + 63) / 64, 256, PROJ_SMEM>>>(src_feat, Wk, bk, Kp, n_src);
    proj_kernel<<<(n_src + 63) / 64, 256, PROJ_SMEM>>>(src_feat, Wv, bv, Vp, n_src);

    int edge_blocks = (E + 7) / 8;   // 8 warps (edges) per 256-thread block
    score_kernel<<<edge_blocks, 256>>>(src_idx, dst_idx, E);
    scatter_kernel<<<edge_blocks, 256>>>(src_idx, dst_idx, out, E);

    int norm_blocks = (n_dst * 32 + 255) / 256;
    normalize_kernel<<<norm_blocks, 256>>>(out, n_dst);
}

// round 3
// speedup vs baseline: 1.5016x; 1.5016x over previous
#include <cuda_runtime.h>
#include <math_constants.h>

// Problem constants (match reference)
#define D         128            // D_IN = D_OUT = 128
#define N_SRC_MAX 50000
#define N_DST_MAX 50000
#define E_MAX     1600000
#define INV_SCALE 0.25f          // 1/sqrt(128/8) = 1/4

// ---------------- scratch (no allocations allowed) ----------------
__device__ __align__(128) float g_Q[N_DST_MAX * D];
__device__ __align__(128) float g_K[N_SRC_MAX * D];
__device__ __align__(128) float g_V[N_SRC_MAX * D];
__device__ __align__(128) int   g_count[N_DST_MAX];
__device__ __align__(128) int   g_start[N_DST_MAX + 1];
__device__ __align__(128) int   g_cursor[N_DST_MAX];
__device__ __align__(128) int   g_perm_src[E_MAX];
__device__ int g_is64;           // 1 if index buffers are int64, 0 if int32

// ---------------- helpers ----------------
__device__ __forceinline__ int load_idx(const void* p, int i) {
    if (g_is64) return (int)((const long long*)p)[i];
    return ((const int*)p)[i];
}

// ---------------- dtype detection: are index buffers int64 or int32? ----------------
__global__ void detect_idx_kernel(const void* src_idx, const void* dst_idx,
                                  int n_src, int n_dst, int E) {
    if (threadIdx.x == 0) g_is64 = 1;
    __syncthreads();
    int i = threadIdx.x;                   // 64 threads
    int limit = (E / 2 < 64) ? E / 2 : 64; // stay within buffer even if int32
    if (i < limit) {
        long long s = ((const long long*)src_idx)[i];
        long long d = ((const long long*)dst_idx)[i];
        bool ok = (s >= 0 && s < n_src && d >= 0 && d < n_dst);
        if (!ok) atomicExch(&g_is64, 0);
    }
}

// ---------------- zero counts ----------------
__global__ void zero_counts_kernel(int n_dst) {
    int i = blockIdx.x * blockDim.x + threadIdx.x;
    if (i < n_dst) g_count[i] = 0;
}

// ---------------- histogram of dst ----------------
__global__ __launch_bounds__(256) void hist_kernel(const void* __restrict__ dst_idx, int E) {
    int i = blockIdx.x * blockDim.x + threadIdx.x;
    if (i < E) {
        int d = load_idx(dst_idx, i);
        atomicAdd(&g_count[d], 1);
    }
}

// ---------------- exclusive prefix scan over g_count (single block) ----------------
__global__ __launch_bounds__(1024) void scan_kernel(int n_dst) {
    __shared__ int sums[1024];
    const int T = 1024;
    int t = threadIdx.x;
    int per = (n_dst + T - 1) / T;
    int begin = t * per;
    int end = begin + per; if (end > n_dst) end = n_dst;

    int local = 0;
    for (int i = begin; i < end && begin < n_dst; i++) local += g_count[i];
    sums[t] = (begin < n_dst) ? local : 0;
    __syncthreads();

    // Hillis-Steele inclusive scan
    for (int off = 1; off < T; off <<= 1) {
        int v = (t >= off) ? sums[t - off] : 0;
        __syncthreads();
        sums[t] += v;
        __syncthreads();
    }

    if (begin < n_dst) {
        int offset = (t == 0) ? 0 : sums[t - 1];
        for (int i = begin; i < end; i++) {
            int c = g_count[i];
            g_start[i]  = offset;
            g_cursor[i] = offset;
            offset += c;
        }
        if (end == n_dst) g_start[n_dst] = offset;
    }
}

// ---------------- permute: bucket src indices by dst ----------------
__global__ __launch_bounds__(256) void permute_kernel(
    const void* __restrict__ src_idx, const void* __restrict__ dst_idx, int E)
{
    int i = blockIdx.x * blockDim.x + threadIdx.x;
    if (i < E) {
        int s = load_idx(src_idx, i);
        int d = load_idx(dst_idx, i);
        int pos = atomicAdd(&g_cursor[d], 1);
        g_perm_src[pos] = s;
    }
}

// ---------------- projection GEMM: Y[n][o] = sum_k X[n][k] * W[o][k] + b[o] ----------------
#define PROJ_SMEM ((64 * 128 + 128 * 132) * 4)
__global__ __launch_bounds__(256) void proj_kernel(
    const float* __restrict__ X, const float* __restrict__ W,
    const float* __restrict__ b, float* __restrict__ Y, int N)
{
    extern __shared__ float sm[];
    float* Xs = sm;               // [64][128]
    float* Wt = sm + 64 * 128;    // [128][132]  (W transposed, padded row)

    const int tid  = threadIdx.x;
    const int row0 = blockIdx.x * 64;

    #pragma unroll 4
    for (int idx = tid; idx < 128 * 128; idx += 256) {
        int o = idx >> 7, k = idx & 127;
        Wt[k * 132 + o] = W[idx];
    }
    #pragma unroll
    for (int idx = tid; idx < 64 * 32; idx += 256) {
        int r = idx >> 5, c4 = idx & 31;
        int row = row0 + r;
        float4 v = (row < N) ? ((const float4*)X)[(size_t)row * 32 + c4]
                             : make_float4(0.f, 0.f, 0.f, 0.f);
        ((float4*)Xs)[r * 32 + c4] = v;
    }
    __syncthreads();

    const int tcol = tid & 31;
    const int trow = tid >> 5;

    float acc[8][4];
    #pragma unroll
    for (int i = 0; i < 8; i++)
        #pragma unroll
        for (int j = 0; j < 4; j++) acc[i][j] = 0.0f;

    #pragma unroll 4
    for (int k = 0; k < 128; k++) {
        float4 w = *(const float4*)&Wt[k * 132 + tcol * 4];
        #pragma unroll
        for (int i = 0; i < 8; i++) {
            float x = Xs[(trow * 8 + i) * 128 + k];
            acc[i][0] += x * w.x;
            acc[i][1] += x * w.y;
            acc[i][2] += x * w.z;
            acc[i][3] += x * w.w;
        }
    }

    float4 bias = *(const float4*)&b[tcol * 4];
    #pragma unroll
    for (int i = 0; i < 8; i++) {
        int row = row0 + trow * 8 + i;
        if (row < N) {
            float4 r4 = make_float4(acc[i][0] + bias.x, acc[i][1] + bias.y,
                                    acc[i][2] + bias.z, acc[i][3] + bias.w);
            ((float4*)Y)[(size_t)row * 32 + tcol] = r4;
        }
    }
}

// ---------------- fused attention: one warp per dst, online softmax ----------------
// No atomics, no scratch score/m/denom arrays, single pass over sorted edges.
__global__ __launch_bounds__(256) void attn_kernel(float* __restrict__ out, int n_dst)
{
    int w = (blockIdx.x * blockDim.x + threadIdx.x) >> 5;   // dst id
    if (w >= n_dst) return;
    int lane = threadIdx.x & 31;

    int start = g_start[w];
    int end   = g_start[w + 1];

    float4 q = ((const float4*)(g_Q + (size_t)w * D))[lane];

    float m = -CUDART_INF_F;
    float denom = 0.0f;
    float4 acc = make_float4(0.f, 0.f, 0.f, 0.f);

    for (int p = start; p < end; ++p) {
        int s = __ldg(&g_perm_src[p]);          // uniform across warp

        float4 k = ((const float4*)(g_K + (size_t)s * D))[lane];
        float4 v = ((const float4*)(g_V + (size_t)s * D))[lane];

        float dot = q.x * k.x + q.y * k.y + q.z * k.z + q.w * k.w;
        #pragma unroll
        for (int off = 16; off > 0; off >>= 1)
            dot += __shfl_xor_sync(0xFFFFFFFFu, dot, off);

        float sc = dot * INV_SCALE;
        float newm = fmaxf(m, sc);
        float scale = __expf(m - newm);         // 1 if no new max; 0 on first iter
        float wgt   = __expf(sc - newm);
        denom = denom * scale + wgt;
        acc.x = acc.x * scale + wgt * v.x;
        acc.y = acc.y * scale + wgt * v.y;
        acc.z = acc.z * scale + wgt * v.z;
        acc.w = acc.w * scale + wgt * v.w;
        m = newm;
    }

    float inv = (denom > 0.0f) ? (1.0f / denom) : 0.0f;
    float4 r = make_float4(acc.x * inv, acc.y * inv, acc.z * inv, acc.w * inv);
    ((float4*)(out + (size_t)w * D))[lane] = r;
}

// ---------------- launch ----------------
extern "C" void kernel_launch(void* const* d_in, const int* in_sizes, int n_in,
                              void* d_out, int out_size)
{
    const float* src_feat = (const float*)d_in[0];
    const float* dst_feat = (const float*)d_in[1];
    const void*  src_idx  = d_in[2];
    const void*  dst_idx  = d_in[3];
    const float* Wq = (const float*)d_in[4];
    const float* bq = (const float*)d_in[5];
    const float* Wk = (const float*)d_in[6];
    const float* bk = (const float*)d_in[7];
    const float* Wv = (const float*)d_in[8];
    const float* bv = (const float*)d_in[9];
    float* out = (float*)d_out;

    int n_src = in_sizes[0] / D;
    int n_dst = in_sizes[1] / D;
    int E     = in_sizes[2];

    static int smem_set = 0;
    if (!smem_set) {
        cudaFuncSetAttribute(proj_kernel, cudaFuncAttributeMaxDynamicSharedMemorySize, PROJ_SMEM);
        smem_set = 1;
    }

    float* Qp; cudaGetSymbolAddress((void**)&Qp, g_Q);
    float* Kp; cudaGetSymbolAddress((void**)&Kp, g_K);
    float* Vp; cudaGetSymbolAddress((void**)&Vp, g_V);

    detect_idx_kernel<<<1, 64>>>(src_idx, dst_idx, n_src, n_dst, E);
    zero_counts_kernel<<<(n_dst + 255) / 256, 256>>>(n_dst);

    proj_kernel<<<(n_dst + 63) / 64, 256, PROJ_SMEM>>>(dst_feat, Wq, bq, Qp, n_dst);
    proj_kernel<<<(n_src + 63) / 64, 256, PROJ_SMEM>>>(src_feat, Wk, bk, Kp, n_src);
    proj_kernel<<<(n_src + 63) / 64, 256, PROJ_SMEM>>>(src_feat, Wv, bv, Vp, n_src);

    hist_kernel<<<(E + 255) / 256, 256>>>(dst_idx, E);
    scan_kernel<<<1, 1024>>>(n_dst);
    permute_kernel<<<(E + 255) / 256, 256>>>(src_idx, dst_idx, E);

    attn_kernel<<<(n_dst + 7) / 8, 256>>>(out, n_dst);
}

// round 5
// speedup vs baseline: 1.5878x; 1.0575x over previous
#include <cuda_runtime.h>
#include <math_constants.h>
#include <cstdint>

// Problem constants (match reference)
#define D         128
#define N_SRC_MAX 50000
#define N_DST_MAX 50000
#define E_MAX     1600000
#define INV_SCALE 0.25f          // 1/sqrt(128/8) = 1/4

// ---------------- scratch (no allocations allowed) ----------------
__device__ __align__(128) float g_Q[N_DST_MAX * D];
__device__ __align__(128) float g_K[N_SRC_MAX * D];
__device__ __align__(128) float g_V[N_SRC_MAX * D];
__device__ __align__(128) int   g_count[N_DST_MAX];
__device__ __align__(128) int   g_start[N_DST_MAX + 1];
__device__ __align__(128) int   g_cursor[N_DST_MAX];
__device__ __align__(128) int   g_perm_src[E_MAX];
__device__ int g_is64;

// ---------------- helpers ----------------
__device__ __forceinline__ int load_idx(const void* p, int i) {
    if (g_is64) return (int)((const long long*)p)[i];
    return ((const int*)p)[i];
}

// packed f32x2 FMA: {d.lo,d.hi} = {a.lo*b.lo+d.lo, a.hi*b.hi+d.hi}
__device__ __forceinline__ void fma2(unsigned long long& d,
                                     unsigned long long a, unsigned long long b) {
    asm("fma.rn.f32x2 %0, %1, %2, %0;" : "+l"(d) : "l"(a), "l"(b));
}
__device__ __forceinline__ unsigned long long pack2(float x) {
    unsigned long long r;
    asm("mov.b64 %0, {%1, %1};" : "=l"(r) : "f"(x));
    return r;
}

// ---------------- dtype detection ----------------
__global__ void detect_idx_kernel(const void* src_idx, const void* dst_idx,
                                  int n_src, int n_dst, int E) {
    if (threadIdx.x == 0) g_is64 = 1;
    __syncthreads();
    int i = threadIdx.x;
    int limit = (E / 2 < 64) ? E / 2 : 64;
    if (i < limit) {
        long long s = ((const long long*)src_idx)[i];
        long long d = ((const long long*)dst_idx)[i];
        bool ok = (s >= 0 && s < n_src && d >= 0 && d < n_dst);
        if (!ok) atomicExch(&g_is64, 0);
    }
}

__global__ void zero_counts_kernel(int n_dst) {
    int i = blockIdx.x * blockDim.x + threadIdx.x;
    if (i < n_dst) g_count[i] = 0;
}

__global__ __launch_bounds__(256) void hist_kernel(const void* __restrict__ dst_idx, int E) {
    int i = blockIdx.x * blockDim.x + threadIdx.x;
    if (i < E) atomicAdd(&g_count[load_idx(dst_idx, i)], 1);
}

__global__ __launch_bounds__(1024) void scan_kernel(int n_dst) {
    __shared__ int sums[1024];
    const int T = 1024;
    int t = threadIdx.x;
    int per = (n_dst + T - 1) / T;
    int begin = t * per;
    int end = begin + per; if (end > n_dst) end = n_dst;

    int local = 0;
    for (int i = begin; i < end && begin < n_dst; i++) local += g_count[i];
    sums[t] = (begin < n_dst) ? local : 0;
    __syncthreads();
    for (int off = 1; off < T; off <<= 1) {
        int v = (t >= off) ? sums[t - off] : 0;
        __syncthreads();
        sums[t] += v;
        __syncthreads();
    }
    if (begin < n_dst) {
        int offset = (t == 0) ? 0 : sums[t - 1];
        for (int i = begin; i < end; i++) {
            int c = g_count[i];
            g_start[i]  = offset;
            g_cursor[i] = offset;
            offset += c;
        }
        if (end == n_dst) g_start[n_dst] = offset;
    }
}

__global__ __launch_bounds__(256) void permute_kernel(
    const void* __restrict__ src_idx, const void* __restrict__ dst_idx, int E)
{
    int i = blockIdx.x * blockDim.x + threadIdx.x;
    if (i < E) {
        int s = load_idx(src_idx, i);
        int d = load_idx(dst_idx, i);
        int pos = atomicAdd(&g_cursor[d], 1);
        g_perm_src[pos] = s;
    }
}

// ---------------- projection GEMM (FFMA2): Y[n][o] = sum_k X[n][k]*W[o][k] + b[o] ----------------
// 64 rows/block, 256 threads. X stored k-major in smem so row-pairs are adjacent:
// one broadcast ld.shared.v2 gives the packed {x_r, x_r+1} operand for fma.rn.f32x2.
#define XT_STRIDE 66                       // 64 rows + 2 pad floats
#define PROJ_SMEM ((128 * XT_STRIDE + 128 * 132) * 4)
__global__ __launch_bounds__(256) void proj_kernel(
    const float* __restrict__ X, const float* __restrict__ W,
    const float* __restrict__ b, float* __restrict__ Y, int N)
{
    extern __shared__ float sm[];
    float* Xt = sm;                        // [128 k][66]  (X transposed)
    float* Wt = sm + 128 * XT_STRIDE;      // [128 k][132] (W transposed, padded)

    const int tid  = threadIdx.x;
    const int row0 = blockIdx.x * 64;

    // Load W (row-major [o][k]) transposed into Wt[k][o]
    #pragma unroll 4
    for (int idx = tid; idx < 128 * 128; idx += 256) {
        int o = idx >> 7, k = idx & 127;
        Wt[k * 132 + o] = W[idx];
    }
    // Load X tile transposed: Xt[k][r] (zero-pad OOB rows)
    #pragma unroll
    for (int idx = tid; idx < 64 * 32; idx += 256) {
        int r = idx >> 5, c4 = idx & 31;
        int row = row0 + r;
        float4 v = (row < N) ? ((const float4*)X)[(size_t)row * 32 + c4]
                             : make_float4(0.f, 0.f, 0.f, 0.f);
        Xt[(c4 * 4 + 0) * XT_STRIDE + r] = v.x;
        Xt[(c4 * 4 + 1) * XT_STRIDE + r] = v.y;
        Xt[(c4 * 4 + 2) * XT_STRIDE + r] = v.z;
        Xt[(c4 * 4 + 3) * XT_STRIDE + r] = v.w;
    }
    __syncthreads();

    const int tcol = tid & 31;    // output cols tcol*4 .. tcol*4+3
    const int trow = tid >> 5;    // rows trow*8 .. trow*8+7 (4 packed pairs)

    unsigned long long acc[4][4]; // [row pair p][col j], packed {row even, row odd}
    #pragma unroll
    for (int p = 0; p < 4; p++)
        #pragma unroll
        for (int j = 0; j < 4; j++) acc[p][j] = 0ULL;

    #pragma unroll 4
    for (int k = 0; k < 128; k++) {
        float4 w = *(const float4*)&Wt[k * 132 + tcol * 4];
        unsigned long long wp0 = pack2(w.x), wp1 = pack2(w.y),
                           wp2 = pack2(w.z), wp3 = pack2(w.w);
        const unsigned long long* xrow =
            (const unsigned long long*)&Xt[k * XT_STRIDE + trow * 8];
        #pragma unroll
        for (int p = 0; p < 4; p++) {
            unsigned long long xp = xrow[p];   // broadcast {x_{2p}, x_{2p+1}}
            fma2(acc[p][0], xp, wp0);
            fma2(acc[p][1], xp, wp1);
            fma2(acc[p][2], xp, wp2);
            fma2(acc[p][3], xp, wp3);
        }
    }

    float4 bias = *(const float4*)&b[tcol * 4];
    #pragma unroll
    for (int p = 0; p < 4; p++) {
        float2 a0 = *(float2*)&acc[p][0];
        float2 a1 = *(float2*)&acc[p][1];
        float2 a2 = *(float2*)&acc[p][2];
        float2 a3 = *(float2*)&acc[p][3];
        int row_e = row0 + trow * 8 + 2 * p;
        if (row_e < N) {
            float4 oe = make_float4(a0.x + bias.x, a1.x + bias.y,
                                    a2.x + bias.z, a3.x + bias.w);
            ((float4*)Y)[(size_t)row_e * 32 + tcol] = oe;
        }
        if (row_e + 1 < N) {
            float4 oo = make_float4(a0.y + bias.x, a1.y + bias.y,
                                    a2.y + bias.z, a3.y + bias.w);
            ((float4*)Y)[(size_t)(row_e + 1) * 32 + tcol] = oo;
        }
    }
}

// ---------------- fused attention: one warp per dst, online softmax ----------------
__global__ __launch_bounds__(256) void attn_kernel(float* __restrict__ out, int n_dst)
{
    int w = (blockIdx.x * blockDim.x + threadIdx.x) >> 5;
    if (w >= n_dst) return;
    int lane = threadIdx.x & 31;

    int start = g_start[w];
    int end   = g_start[w + 1];

    float4 q = ((const float4*)(g_Q + (size_t)w * D))[lane];

    float m = -CUDART_INF_F;
    float denom = 0.0f;
    float4 acc = make_float4(0.f, 0.f, 0.f, 0.f);

    for (int p = start; p < end; ++p) {
        int s = __ldg(&g_perm_src[p]);

        float4 k = ((const float4*)(g_K + (size_t)s * D))[lane];
        float4 v = ((const float4*)(g_V + (size_t)s * D))[lane];

        float dot = q.x * k.x + q.y * k.y + q.z * k.z + q.w * k.w;
        #pragma unroll
        for (int off = 16; off > 0; off >>= 1)
            dot += __shfl_xor_sync(0xFFFFFFFFu, dot, off);

        float sc = dot * INV_SCALE;
        float newm = fmaxf(m, sc);
        float scale = __expf(m - newm);
        float wgt   = __expf(sc - newm);
        denom = denom * scale + wgt;
        acc.x = acc.x * scale + wgt * v.x;
        acc.y = acc.y * scale + wgt * v.y;
        acc.z = acc.z * scale + wgt * v.z;
        acc.w = acc.w * scale + wgt * v.w;
        m = newm;
    }

    float inv = (denom > 0.0f) ? (1.0f / denom) : 0.0f;
    float4 r = make_float4(acc.x * inv, acc.y * inv, acc.z * inv, acc.w * inv);
    ((float4*)(out + (size_t)w * D))[lane] = r;
}

// ---------------- launch ----------------
extern "C" void kernel_launch(void* const* d_in, const int* in_sizes, int n_in,
                              void* d_out, int out_size)
{
    const float* src_feat = (const float*)d_in[0];
    const float* dst_feat = (const float*)d_in[1];
    const void*  src_idx  = d_in[2];
    const void*  dst_idx  = d_in[3];
    const float* Wq = (const float*)d_in[4];
    const float* bq = (const float*)d_in[5];
    const float* Wk = (const float*)d_in[6];
    const float* bk = (const float*)d_in[7];
    const float* Wv = (const float*)d_in[8];
    const float* bv = (const float*)d_in[9];
    float* out = (float*)d_out;

    int n_src = in_sizes[0] / D;
    int n_dst = in_sizes[1] / D;
    int E     = in_sizes[2];

    static int attr_set = 0;
    if (!attr_set) {
        cudaFuncSetAttribute(proj_kernel, cudaFuncAttributeMaxDynamicSharedMemorySize, PROJ_SMEM);
        attr_set = 1;
    }

    float* Qp; cudaGetSymbolAddress((void**)&Qp, g_Q);
    float* Kp; cudaGetSymbolAddress((void**)&Kp, g_K);
    float* Vp; cudaGetSymbolAddress((void**)&Vp, g_V);

    detect_idx_kernel<<<1, 64>>>(src_idx, dst_idx, n_src, n_dst, E);
    zero_counts_kernel<<<(n_dst + 255) / 256, 256>>>(n_dst);

    proj_kernel<<<(n_dst + 63) / 64, 256, PROJ_SMEM>>>(dst_feat, Wq, bq, Qp, n_dst);
    proj_kernel<<<(n_src + 63) / 64, 256, PROJ_SMEM>>>(src_feat, Wk, bk, Kp, n_src);
    proj_kernel<<<(n_src + 63) / 64, 256, PROJ_SMEM>>>(src_feat, Wv, bv, Vp, n_src);

    hist_kernel<<<(E + 255) / 256, 256>>>(dst_idx, E);
    scan_kernel<<<1, 1024>>>(n_dst);
    permute_kernel<<<(E + 255) / 256, 256>>>(src_idx, dst_idx, E);

    attn_kernel<<<(n_dst + 7) / 8, 256>>>(out, n_dst);
}

// round 7
// speedup vs baseline: 2.0484x; 1.2901x over previous
#include <cuda_runtime.h>
#include <math_constants.h>
#include <cstdint>

// Problem constants (match reference)
#define D         128
#define N_SRC_MAX 50000
#define N_DST_MAX 50000
#define E_MAX     1600000
#define INV_SCALE 0.25f          // 1/sqrt(128/8) = 1/4

// ---------------- scratch (no allocations allowed) ----------------
__device__ __align__(128) float g_Q[N_DST_MAX * D];
__device__ __align__(128) float g_K[N_SRC_MAX * D];
__device__ __align__(128) float g_V[N_SRC_MAX * D];
__device__ __align__(128) int   g_count[N_DST_MAX];
__device__ __align__(128) int   g_start[N_DST_MAX + 1];
__device__ __align__(128) int   g_cursor[N_DST_MAX];
__device__ __align__(128) int   g_perm_src[E_MAX];
__device__ int g_is64;

// ---------------- helpers ----------------
__device__ __forceinline__ int load_idx(const void* p, int i) {
    if (g_is64) return (int)((const long long*)p)[i];
    return ((const int*)p)[i];
}

// packed f32x2 FMA: {d.lo,d.hi} = {a.lo*b.lo+d.lo, a.hi*b.hi+d.hi}
__device__ __forceinline__ void fma2(unsigned long long& d,
                                     unsigned long long a, unsigned long long b) {
    asm("fma.rn.f32x2 %0, %1, %2, %0;" : "+l"(d) : "l"(a), "l"(b));
}
__device__ __forceinline__ unsigned long long pack2(float x) {
    unsigned long long r;
    asm("mov.b64 %0, {%1, %1};" : "=l"(r) : "f"(x));
    return r;
}

// ---------------- dtype detection ----------------
__global__ void detect_idx_kernel(const void* src_idx, const void* dst_idx,
                                  int n_src, int n_dst, int E) {
    if (threadIdx.x == 0) g_is64 = 1;
    __syncthreads();
    int i = threadIdx.x;
    int limit = (E / 2 < 64) ? E / 2 : 64;
    if (i < limit) {
        long long s = ((const long long*)src_idx)[i];
        long long d = ((const long long*)dst_idx)[i];
        bool ok = (s >= 0 && s < n_src && d >= 0 && d < n_dst);
        if (!ok) atomicExch(&g_is64, 0);
    }
}

__global__ void zero_counts_kernel(int n_dst) {
    int i = blockIdx.x * blockDim.x + threadIdx.x;
    if (i < n_dst) g_count[i] = 0;
}

__global__ __launch_bounds__(256) void hist_kernel(const void* __restrict__ dst_idx, int E) {
    int i = blockIdx.x * blockDim.x + threadIdx.x;
    if (i < E) atomicAdd(&g_count[load_idx(dst_idx, i)], 1);
}

__global__ __launch_bounds__(1024) void scan_kernel(int n_dst) {
    __shared__ int sums[1024];
    const int T = 1024;
    int t = threadIdx.x;
    int per = (n_dst + T - 1) / T;
    int begin = t * per;
    int end = begin + per; if (end > n_dst) end = n_dst;

    int local = 0;
    for (int i = begin; i < end && begin < n_dst; i++) local += g_count[i];
    sums[t] = (begin < n_dst) ? local : 0;
    __syncthreads();
    for (int off = 1; off < T; off <<= 1) {
        int v = (t >= off) ? sums[t - off] : 0;
        __syncthreads();
        sums[t] += v;
        __syncthreads();
    }
    if (begin < n_dst) {
        int offset = (t == 0) ? 0 : sums[t - 1];
        for (int i = begin; i < end; i++) {
            int c = g_count[i];
            g_start[i]  = offset;
            g_cursor[i] = offset;
            offset += c;
        }
        if (end == n_dst) g_start[n_dst] = offset;
    }
}

__global__ __launch_bounds__(256) void permute_kernel(
    const void* __restrict__ src_idx, const void* __restrict__ dst_idx, int E)
{
    int i = blockIdx.x * blockDim.x + threadIdx.x;
    if (i < E) {
        int s = load_idx(src_idx, i);
        int d = load_idx(dst_idx, i);
        int pos = atomicAdd(&g_cursor[d], 1);
        g_perm_src[pos] = s;
    }
}

// ---------------- projection GEMM (FFMA2): Y[n][o] = sum_k X[n][k]*W[o][k] + b[o] ----------------
// 64 rows/block, 256 threads. X stored k-major in smem so row-pairs are adjacent:
// one broadcast ld.shared.v2 gives the packed {x_r, x_r+1} operand for fma.rn.f32x2.
// NOTE: strides must keep vector alignment: XT_STRIDE even (8B loads), WT_STRIDE %4==0 (16B loads).
#define XT_STRIDE 66
#define WT_STRIDE 132
#define PROJ_SMEM ((128 * XT_STRIDE + 128 * WT_STRIDE) * 4)
__global__ __launch_bounds__(256) void proj_kernel(
    const float* __restrict__ X, const float* __restrict__ W,
    const float* __restrict__ b, float* __restrict__ Y, int N)
{
    extern __shared__ float sm[];
    float* Xt = sm;                        // [128 k][66]  (X transposed)
    float* Wt = sm + 128 * XT_STRIDE;      // [128 k][132] (W transposed)

    const int tid  = threadIdx.x;
    const int row0 = blockIdx.x * 64;

    // Load W (row-major [o][k]) transposed into Wt[k][o]
    #pragma unroll 4
    for (int idx = tid; idx < 128 * 128; idx += 256) {
        int o = idx >> 7, k = idx & 127;
        Wt[k * WT_STRIDE + o] = W[idx];
    }
    // Load X tile transposed: Xt[k][r] (zero-pad OOB rows)
    #pragma unroll
    for (int idx = tid; idx < 64 * 32; idx += 256) {
        int r = idx >> 5, c4 = idx & 31;
        int row = row0 + r;
        float4 v = (row < N) ? ((const float4*)X)[(size_t)row * 32 + c4]
                             : make_float4(0.f, 0.f, 0.f, 0.f);
        Xt[(c4 * 4 + 0) * XT_STRIDE + r] = v.x;
        Xt[(c4 * 4 + 1) * XT_STRIDE + r] = v.y;
        Xt[(c4 * 4 + 2) * XT_STRIDE + r] = v.z;
        Xt[(c4 * 4 + 3) * XT_STRIDE + r] = v.w;
    }
    __syncthreads();

    const int tcol = tid & 31;    // output cols tcol*4 .. tcol*4+3
    const int trow = tid >> 5;    // rows trow*8 .. trow*8+7 (4 packed pairs)

    unsigned long long acc[4][4]; // [row pair p][col j], packed {row even, row odd}
    #pragma unroll
    for (int p = 0; p < 4; p++)
        #pragma unroll
        for (int j = 0; j < 4; j++) acc[p][j] = 0ULL;

    #pragma unroll 4
    for (int k = 0; k < 128; k++) {
        float4 w = *(const float4*)&Wt[k * WT_STRIDE + tcol * 4];
        unsigned long long wp0 = pack2(w.x), wp1 = pack2(w.y),
                           wp2 = pack2(w.z), wp3 = pack2(w.w);
        const unsigned long long* xrow =
            (const unsigned long long*)&Xt[k * XT_STRIDE + trow * 8];
        #pragma unroll
        for (int p = 0; p < 4; p++) {
            unsigned long long xp = xrow[p];   // broadcast {x_{2p}, x_{2p+1}}
            fma2(acc[p][0], xp, wp0);
            fma2(acc[p][1], xp, wp1);
            fma2(acc[p][2], xp, wp2);
            fma2(acc[p][3], xp, wp3);
        }
    }

    float4 bias = *(const float4*)&b[tcol * 4];
    #pragma unroll
    for (int p = 0; p < 4; p++) {
        float2 a0 = *(float2*)&acc[p][0];
        float2 a1 = *(float2*)&acc[p][1];
        float2 a2 = *(float2*)&acc[p][2];
        float2 a3 = *(float2*)&acc[p][3];
        int row_e = row0 + trow * 8 + 2 * p;
        if (row_e < N) {
            float4 oe = make_float4(a0.x + bias.x, a1.x + bias.y,
                                    a2.x + bias.z, a3.x + bias.w);
            ((float4*)Y)[(size_t)row_e * 32 + tcol] = oe;
        }
        if (row_e + 1 < N) {
            float4 oo = make_float4(a0.y + bias.x, a1.y + bias.y,
                                    a2.y + bias.z, a3.y + bias.w);
            ((float4*)Y)[(size_t)(row_e + 1) * 32 + tcol] = oo;
        }
    }
}

// ---------------- fused attention: one warp per dst, online softmax ----------------
__global__ __launch_bounds__(256) void attn_kernel(float* __restrict__ out, int n_dst)
{
    int w = (blockIdx.x * blockDim.x + threadIdx.x) >> 5;
    if (w >= n_dst) return;
    int lane = threadIdx.x & 31;

    int start = g_start[w];
    int end   = g_start[w + 1];

    float4 q = ((const float4*)(g_Q + (size_t)w * D))[lane];

    float m = -CUDART_INF_F;
    float denom = 0.0f;
    float4 acc = make_float4(0.f, 0.f, 0.f, 0.f);

    for (int p = start; p < end; ++p) {
        int s = __ldg(&g_perm_src[p]);

        float4 k = ((const float4*)(g_K + (size_t)s * D))[lane];
        float4 v = ((const float4*)(g_V + (size_t)s * D))[lane];

        float dot = q.x * k.x + q.y * k.y + q.z * k.z + q.w * k.w;
        #pragma unroll
        for (int off = 16; off > 0; off >>= 1)
            dot += __shfl_xor_sync(0xFFFFFFFFu, dot, off);

        float sc = dot * INV_SCALE;
        float newm = fmaxf(m, sc);
        float scale = __expf(m - newm);
        float wgt   = __expf(sc - newm);
        denom = denom * scale + wgt;
        acc.x = acc.x * scale + wgt * v.x;
        acc.y = acc.y * scale + wgt * v.y;
        acc.z = acc.z * scale + wgt * v.z;
        acc.w = acc.w * scale + wgt * v.w;
        m = newm;
    }

    float inv = (denom > 0.0f) ? (1.0f / denom) : 0.0f;
    float4 r = make_float4(acc.x * inv, acc.y * inv, acc.z * inv, acc.w * inv);
    ((float4*)(out + (size_t)w * D))[lane] = r;
}

// ---------------- launch: fork-join two streams so the sort chain hides under proj ----------------
extern "C" void kernel_launch(void* const* d_in, const int* in_sizes, int n_in,
                              void* d_out, int out_size)
{
    const float* src_feat = (const float*)d_in[0];
    const float* dst_feat = (const float*)d_in[1];
    const void*  src_idx  = d_in[2];
    const void*  dst_idx  = d_in[3];
    const float* Wq = (const float*)d_in[4];
    const float* bq = (const float*)d_in[5];
    const float* Wk = (const float*)d_in[6];
    const float* bk = (const float*)d_in[7];
    const float* Wv = (const float*)d_in[8];
    const float* bv = (const float*)d_in[9];
    float* out = (float*)d_out;

    int n_src = in_sizes[0] / D;
    int n_dst = in_sizes[1] / D;
    int E     = in_sizes[2];

    static cudaStream_t s2 = nullptr;
    static cudaEvent_t evFork = nullptr, evJoin = nullptr;
    static int attr_set = 0;
    if (!attr_set) {
        cudaFuncSetAttribute(proj_kernel, cudaFuncAttributeMaxDynamicSharedMemorySize, PROJ_SMEM);
        cudaStreamCreateWithFlags(&s2, cudaStreamNonBlocking);
        cudaEventCreateWithFlags(&evFork, cudaEventDisableTiming);
        cudaEventCreateWithFlags(&evJoin, cudaEventDisableTiming);
        attr_set = 1;
    }

    float* Qp; cudaGetSymbolAddress((void**)&Qp, g_Q);
    float* Kp; cudaGetSymbolAddress((void**)&Kp, g_K);
    float* Vp; cudaGetSymbolAddress((void**)&Vp, g_V);

    // Fork: stream B (s2) handles the index/sort chain, independent of projections.
    cudaEventRecord(evFork, 0);
    cudaStreamWaitEvent(s2, evFork, 0);

    detect_idx_kernel<<<1, 64, 0, s2>>>(src_idx, dst_idx, n_src, n_dst, E);
    zero_counts_kernel<<<(n_dst + 255) / 256, 256, 0, s2>>>(n_dst);
    hist_kernel<<<(E + 255) / 256, 256, 0, s2>>>(dst_idx, E);
    scan_kernel<<<1, 1024, 0, s2>>>(n_dst);
    permute_kernel<<<(E + 255) / 256, 256, 0, s2>>>(src_idx, dst_idx, E);
    cudaEventRecord(evJoin, s2);

    // Stream A (capture stream): the three projections.
    proj_kernel<<<(n_dst + 63) / 64, 256, PROJ_SMEM>>>(dst_feat, Wq, bq, Qp, n_dst);
    proj_kernel<<<(n_src + 63) / 64, 256, PROJ_SMEM>>>(src_feat, Wk, bk, Kp, n_src);
    proj_kernel<<<(n_src + 63) / 64, 256, PROJ_SMEM>>>(src_feat, Wv, bv, Vp, n_src);

    // Join: attention needs Q/K/V and the sorted edge lists.
    cudaStreamWaitEvent(0, evJoin, 0);
    attn_kernel<<<(n_dst + 7) / 8, 256>>>(out, n_dst);
}

// round 8
// speedup vs baseline: 2.2048x; 1.0763x over previous
#include <cuda_runtime.h>
#include <cuda_fp16.h>
#include <math_constants.h>
#include <cstdint>

// Problem constants (match reference)
#define D         128
#define N_SRC_MAX 50000
#define N_DST_MAX 50000
#define E_MAX     1600000
#define INV_SCALE 0.25f          // 1/sqrt(128/8) = 1/4

// ---------------- scratch (no allocations allowed) ----------------
__device__ __align__(128) float  g_Q[N_DST_MAX * D];
__device__ __align__(128) float  g_K[N_SRC_MAX * D];
__device__ __align__(128) __half g_Vh[N_SRC_MAX * D];
__device__ __align__(128) int    g_count[N_DST_MAX];
__device__ __align__(128) int    g_start[N_DST_MAX + 1];
__device__ __align__(128) int    g_cursor[N_DST_MAX];
__device__ __align__(128) int    g_perm_src[E_MAX];
__device__ __align__(128) int    g_bsum[128];
__device__ int g_is64;

// ---------------- helpers ----------------
__device__ __forceinline__ int load_idx(const void* p, int i) {
    if (g_is64) return (int)((const long long*)p)[i];
    return ((const int*)p)[i];
}
__device__ __forceinline__ void fma2(unsigned long long& d,
                                     unsigned long long a, unsigned long long b) {
    asm("fma.rn.f32x2 %0, %1, %2, %0;" : "+l"(d) : "l"(a), "l"(b));
}
__device__ __forceinline__ unsigned long long pack2(float x) {
    unsigned long long r;
    asm("mov.b64 %0, {%1, %1};" : "=l"(r) : "f"(x));
    return r;
}

// ---------------- dtype detection ----------------
__global__ void detect_idx_kernel(const void* src_idx, const void* dst_idx,
                                  int n_src, int n_dst, int E) {
    if (threadIdx.x == 0) g_is64 = 1;
    __syncthreads();
    int i = threadIdx.x;
    int limit = (E / 2 < 64) ? E / 2 : 64;
    if (i < limit) {
        long long s = ((const long long*)src_idx)[i];
        long long d = ((const long long*)dst_idx)[i];
        bool ok = (s >= 0 && s < n_src && d >= 0 && d < n_dst);
        if (!ok) atomicExch(&g_is64, 0);
    }
}

__global__ void zero_counts_kernel(int n_dst) {
    int i = blockIdx.x * blockDim.x + threadIdx.x;
    if (i < n_dst) g_count[i] = 0;
}

__global__ __launch_bounds__(256) void hist_kernel(const void* __restrict__ dst_idx, int E) {
    int i = blockIdx.x * blockDim.x + threadIdx.x;
    if (i < E) atomicAdd(&g_count[load_idx(dst_idx, i)], 1);
}

// ---------------- parallel exclusive scan (3 kernels, 1024 elems/block) ----------------
__global__ __launch_bounds__(256) void scan_bsum_kernel(int n_dst) {
    int t = threadIdx.x;
    int base = blockIdx.x * 1024 + t * 4;
    int v = 0;
    #pragma unroll
    for (int j = 0; j < 4; j++) {
        int i = base + j;
        if (i < n_dst) v += g_count[i];
    }
    #pragma unroll
    for (int off = 16; off; off >>= 1) v += __shfl_xor_sync(0xFFFFFFFFu, v, off);
    __shared__ int ws[8];
    if ((t & 31) == 0) ws[t >> 5] = v;
    __syncthreads();
    if (t < 8) {
        int u = ws[t];
        #pragma unroll
        for (int off = 4; off; off >>= 1) u += __shfl_xor_sync(0xFFu, u, off);
        if (t == 0) g_bsum[blockIdx.x] = u;
    }
}

__global__ __launch_bounds__(128) void scan_top_kernel(int nblocks) {
    __shared__ int s[128];
    int t = threadIdx.x;
    s[t] = (t < nblocks) ? g_bsum[t] : 0;
    __syncthreads();
    for (int off = 1; off < 128; off <<= 1) {
        int v = (t >= off) ? s[t - off] : 0;
        __syncthreads();
        s[t] += v;
        __syncthreads();
    }
    int excl = (t == 0) ? 0 : s[t - 1];
    if (t < nblocks) g_bsum[t] = excl;
}

__global__ __launch_bounds__(256) void scan_apply_kernel(int n_dst, int E) {
    __shared__ int ws[8];
    int t = threadIdx.x;
    int lane = t & 31, wid = t >> 5;
    int base = blockIdx.x * 1024 + t * 4;
    int c[4];
    int s_local = 0;
    #pragma unroll
    for (int j = 0; j < 4; j++) {
        int i = base + j;
        c[j] = (i < n_dst) ? g_count[i] : 0;
        s_local += c[j];
    }
    int v = s_local;
    #pragma unroll
    for (int off = 1; off < 32; off <<= 1) {
        int u = __shfl_up_sync(0xFFFFFFFFu, v, off);
        if (lane >= off) v += u;
    }
    if (lane == 31) ws[wid] = v;
    __syncthreads();
    if (t < 8) {
        int u = ws[t];
        #pragma unroll
        for (int off = 1; off < 8; off <<= 1) {
            int x = __shfl_up_sync(0xFFu, u, off);
            if (t >= off) u += x;
        }
        ws[t] = u;
    }
    __syncthreads();
    int run = v - s_local + (wid ? ws[wid - 1] : 0) + g_bsum[blockIdx.x];
    #pragma unroll
    for (int j = 0; j < 4; j++) {
        int i = base + j;
        if (i < n_dst) {
            g_start[i]  = run;
            g_cursor[i] = run;
            run += c[j];
        }
    }
    if (blockIdx.x == 0 && t == 0) g_start[n_dst] = E;
}

__global__ __launch_bounds__(256) void permute_kernel(
    const void* __restrict__ src_idx, const void* __restrict__ dst_idx, int E)
{
    int i = blockIdx.x * blockDim.x + threadIdx.x;
    if (i < E) {
        int s = load_idx(src_idx, i);
        int d = load_idx(dst_idx, i);
        int pos = atomicAdd(&g_cursor[d], 1);
        g_perm_src[pos] = s;
    }
}

// ---------------- merged projection GEMM (FFMA2), all 3 matrices in one launch ----------------
#define XT_STRIDE 66
#define WT_STRIDE 132
#define PROJ_SMEM ((128 * XT_STRIDE + 128 * WT_STRIDE) * 4)
__global__ __launch_bounds__(256) void proj3_kernel(
    const float* __restrict__ dst_feat, const float* __restrict__ src_feat,
    const float* __restrict__ Wq, const float* __restrict__ bq_,
    const float* __restrict__ Wk, const float* __restrict__ bk_,
    const float* __restrict__ Wv, const float* __restrict__ bv_,
    int n_dst, int n_src, int blocks_q, int blocks_k)
{
    extern __shared__ float sm[];
    float* Xt = sm;                        // [128 k][66]
    float* Wt = sm + 128 * XT_STRIDE;      // [128 k][132]

    const int tid = threadIdx.x;
    const int bid = blockIdx.x;

    const float *X, *W, *B;
    float* Y = nullptr;
    int N, row0;
    bool v_half = false;
    if (bid < blocks_q) {
        X = dst_feat; W = Wq; B = bq_; Y = g_Q; N = n_dst; row0 = bid * 64;
    } else if (bid < blocks_q + blocks_k) {
        X = src_feat; W = Wk; B = bk_; Y = g_K; N = n_src; row0 = (bid - blocks_q) * 64;
    } else {
        X = src_feat; W = Wv; B = bv_; N = n_src; row0 = (bid - blocks_q - blocks_k) * 64;
        v_half = true;
    }

    #pragma unroll 4
    for (int idx = tid; idx < 128 * 128; idx += 256) {
        int o = idx >> 7, k = idx & 127;
        Wt[k * WT_STRIDE + o] = W[idx];
    }
    #pragma unroll
    for (int idx = tid; idx < 64 * 32; idx += 256) {
        int r = idx >> 5, c4 = idx & 31;
        int row = row0 + r;
        float4 v = (row < N) ? ((const float4*)X)[(size_t)row * 32 + c4]
                             : make_float4(0.f, 0.f, 0.f, 0.f);
        Xt[(c4 * 4 + 0) * XT_STRIDE + r] = v.x;
        Xt[(c4 * 4 + 1) * XT_STRIDE + r] = v.y;
        Xt[(c4 * 4 + 2) * XT_STRIDE + r] = v.z;
        Xt[(c4 * 4 + 3) * XT_STRIDE + r] = v.w;
    }
    __syncthreads();

    const int tcol = tid & 31;
    const int trow = tid >> 5;

    unsigned long long acc[4][4];
    #pragma unroll
    for (int p = 0; p < 4; p++)
        #pragma unroll
        for (int j = 0; j < 4; j++) acc[p][j] = 0ULL;

    #pragma unroll 4
    for (int k = 0; k < 128; k++) {
        float4 w = *(const float4*)&Wt[k * WT_STRIDE + tcol * 4];
        unsigned long long wp0 = pack2(w.x), wp1 = pack2(w.y),
                           wp2 = pack2(w.z), wp3 = pack2(w.w);
        const unsigned long long* xrow =
            (const unsigned long long*)&Xt[k * XT_STRIDE + trow * 8];
        #pragma unroll
        for (int p = 0; p < 4; p++) {
            unsigned long long xp = xrow[p];
            fma2(acc[p][0], xp, wp0);
            fma2(acc[p][1], xp, wp1);
            fma2(acc[p][2], xp, wp2);
            fma2(acc[p][3], xp, wp3);
        }
    }

    float4 bias = *(const float4*)&B[tcol * 4];
    #pragma unroll
    for (int p = 0; p < 4; p++) {
        float2 a0 = *(float2*)&acc[p][0];
        float2 a1 = *(float2*)&acc[p][1];
        float2 a2 = *(float2*)&acc[p][2];
        float2 a3 = *(float2*)&acc[p][3];
        int row_e = row0 + trow * 8 + 2 * p;
        float4 oe = make_float4(a0.x + bias.x, a1.x + bias.y, a2.x + bias.z, a3.x + bias.w);
        float4 oo = make_float4(a0.y + bias.x, a1.y + bias.y, a2.y + bias.z, a3.y + bias.w);
        if (v_half) {
            if (row_e < N) {
                __half2 h0 = __floats2half2_rn(oe.x, oe.y);
                __half2 h1 = __floats2half2_rn(oe.z, oe.w);
                uint2 u; u.x = *(uint32_t*)&h0; u.y = *(uint32_t*)&h1;
                ((uint2*)(g_Vh + (size_t)row_e * 128))[tcol] = u;
            }
            if (row_e + 1 < N) {
                __half2 h0 = __floats2half2_rn(oo.x, oo.y);
                __half2 h1 = __floats2half2_rn(oo.z, oo.w);
                uint2 u; u.x = *(uint32_t*)&h0; u.y = *(uint32_t*)&h1;
                ((uint2*)(g_Vh + (size_t)(row_e + 1) * 128))[tcol] = u;
            }
        } else {
            if (row_e < N)     ((float4*)Y)[(size_t)row_e * 32 + tcol] = oe;
            if (row_e + 1 < N) ((float4*)Y)[(size_t)(row_e + 1) * 32 + tcol] = oo;
        }
    }
}

// ---------------- fused attention: one warp per dst, online softmax ----------------
__global__ __launch_bounds__(256) void attn_kernel(float* __restrict__ out, int n_dst)
{
    int w = (blockIdx.x * blockDim.x + threadIdx.x) >> 5;
    if (w >= n_dst) return;
    int lane = threadIdx.x & 31;

    int start = g_start[w];
    int end   = g_start[w + 1];

    float4 q = ((const float4*)(g_Q + (size_t)w * D))[lane];

    float m = -CUDART_INF_F;
    float denom = 0.0f;
    float4 acc = make_float4(0.f, 0.f, 0.f, 0.f);

    for (int p = start; p < end; ++p) {
        int s = __ldg(&g_perm_src[p]);

        float4 k = ((const float4*)(g_K + (size_t)s * D))[lane];
        uint2 vv = ((const uint2*)(g_Vh + (size_t)s * D))[lane];
        float2 v01 = __half22float2(*(__half2*)&vv.x);
        float2 v23 = __half22float2(*(__half2*)&vv.y);

        float dot = q.x * k.x + q.y * k.y + q.z * k.z + q.w * k.w;
        #pragma unroll
        for (int off = 16; off > 0; off >>= 1)
            dot += __shfl_xor_sync(0xFFFFFFFFu, dot, off);

        float sc = dot * INV_SCALE;
        float newm = fmaxf(m, sc);
        float scale = __expf(m - newm);
        float wgt   = __expf(sc - newm);
        denom = denom * scale + wgt;
        acc.x = acc.x * scale + wgt * v01.x;
        acc.y = acc.y * scale + wgt * v01.y;
        acc.z = acc.z * scale + wgt * v23.x;
        acc.w = acc.w * scale + wgt * v23.y;
        m = newm;
    }

    float inv = (denom > 0.0f) ? (1.0f / denom) : 0.0f;
    float4 r = make_float4(acc.x * inv, acc.y * inv, acc.z * inv, acc.w * inv);
    ((float4*)(out + (size_t)w * D))[lane] = r;
}

// ---------------- launch: fork-join two streams ----------------
extern "C" void kernel_launch(void* const* d_in, const int* in_sizes, int n_in,
                              void* d_out, int out_size)
{
    const float* src_feat = (const float*)d_in[0];
    const float* dst_feat = (const float*)d_in[1];
    const void*  src_idx  = d_in[2];
    const void*  dst_idx  = d_in[3];
    const float* Wq = (const float*)d_in[4];
    const float* bq = (const float*)d_in[5];
    const float* Wk = (const float*)d_in[6];
    const float* bk = (const float*)d_in[7];
    const float* Wv = (const float*)d_in[8];
    const float* bv = (const float*)d_in[9];
    float* out = (float*)d_out;

    int n_src = in_sizes[0] / D;
    int n_dst = in_sizes[1] / D;
    int E     = in_sizes[2];

    static cudaStream_t s2 = nullptr;
    static cudaEvent_t evFork = nullptr, evJoin = nullptr;
    static int attr_set = 0;
    if (!attr_set) {
        cudaFuncSetAttribute(proj3_kernel, cudaFuncAttributeMaxDynamicSharedMemorySize, PROJ_SMEM);
        cudaStreamCreateWithFlags(&s2, cudaStreamNonBlocking);
        cudaEventCreateWithFlags(&evFork, cudaEventDisableTiming);
        cudaEventCreateWithFlags(&evJoin, cudaEventDisableTiming);
        attr_set = 1;
    }

    // Fork: stream B handles the index/sort chain.
    cudaEventRecord(evFork, 0);
    cudaStreamWaitEvent(s2, evFork, 0);

    detect_idx_kernel<<<1, 64, 0, s2>>>(src_idx, dst_idx, n_src, n_dst, E);
    zero_counts_kernel<<<(n_dst + 255) / 256, 256, 0, s2>>>(n_dst);
    hist_kernel<<<(E + 255) / 256, 256, 0, s2>>>(dst_idx, E);
    int scan_blocks = (n_dst + 1023) / 1024;
    scan_bsum_kernel<<<scan_blocks, 256, 0, s2>>>(n_dst);
    scan_top_kernel<<<1, 128, 0, s2>>>(scan_blocks);
    scan_apply_kernel<<<scan_blocks, 256, 0, s2>>>(n_dst, E);
    permute_kernel<<<(E + 255) / 256, 256, 0, s2>>>(src_idx, dst_idx, E);
    cudaEventRecord(evJoin, s2);

    // Stream A: merged projections (Q, K fp32; V fp16).
    int blocks_q = (n_dst + 63) / 64;
    int blocks_k = (n_src + 63) / 64;
    int blocks_v = (n_src + 63) / 64;
    proj3_kernel<<<blocks_q + blocks_k + blocks_v, 256, PROJ_SMEM>>>(
        dst_feat, src_feat, Wq, bq, Wk, bk, Wv, bv, n_dst, n_src, blocks_q, blocks_k);

    // Join: attention needs Q/K/V and the sorted edge lists.
    cudaStreamWaitEvent(0, evJoin, 0);
    attn_kernel<<<(n_dst + 7) / 8, 256>>>(out, n_dst);
}